// round 1
// baseline (speedup 1.0000x reference)
#include <cuda_runtime.h>
#include <cuda_bf16.h>

// Problem constants
#define BB   1024
#define CC   256
#define HH   16
#define WW   24
#define HWL  384      // H*W
#define NOBJ 10
#define DD   256

// Scratch (device globals: no allocation allowed)
__device__ float g_fused[(size_t)BB * HWL * CC];        // [B][HW][C]  402 MB
__device__ float g_scores[(size_t)BB * NOBJ * HWL];     // [B][N][HW]  15.7 MB

// ---------------- cp.async helpers ----------------
__device__ __forceinline__ void cp_async16(void* smem, const void* g) {
    unsigned s = (unsigned)__cvta_generic_to_shared(smem);
    asm volatile("cp.async.cg.shared.global [%0], [%1], 16;\n" :: "r"(s), "l"(g));
}
__device__ __forceinline__ void cp_commit() { asm volatile("cp.async.commit_group;\n" ::: "memory"); }
__device__ __forceinline__ void cp_wait0()  { asm volatile("cp.async.wait_group 0;\n" ::: "memory"); }
__device__ __forceinline__ void cp_wait1()  { asm volatile("cp.async.wait_group 1;\n" ::: "memory"); }

// =====================================================================
// K1: per-batch conv-fuse GEMM (+coords+bias+ReLU) + scores epilogue
//   fused[b][hw][d] = relu( sum_c input[b][c][hw]*Wc[c][d]
//                           + xc(hw)*Wc[256][d] + yc(hw)*Wc[257][d] + bias[d] )
//   scores[b][n][hw] = sum_d query[n][d]*fused[b][hw][d]
// Tile: BM=64 (hw) x BN=256 (all d) x BK=16. 256 threads, 8x8 per thread.
// =====================================================================
__global__ __launch_bounds__(256, 2)
void k1_conv_scores(const float* __restrict__ input,
                    const float* __restrict__ conv_w,
                    const float* __restrict__ conv_b,
                    const float* __restrict__ query) {
    __shared__ __align__(16) float As[2][16][64];
    __shared__ __align__(16) float Bs[2][16][256];

    const int b   = blockIdx.y;
    const int hw0 = blockIdx.x * 64;
    const int tid = threadIdx.x;
    const int tx  = tid & 31;
    const int ty  = tid >> 5;

    const float* Ab = input + (size_t)b * (CC * HWL) + hw0;  // A[c][hw], row stride HWL

    float acc[8][8];
#pragma unroll
    for (int i = 0; i < 8; i++)
#pragma unroll
        for (int j = 0; j < 8; j++) acc[i][j] = 0.f;

#define K1_ISSUE(K0, BUF) do {                                                    \
        int arow_ = tid >> 4, ac_ = (tid & 15) << 2;                              \
        cp_async16(&As[BUF][arow_][ac_], Ab + (size_t)((K0) + arow_) * HWL + ac_);\
        _Pragma("unroll")                                                          \
        for (int r_ = 0; r_ < 4; r_++) {                                          \
            int f_ = tid + (r_ << 8);                                             \
            int brow_ = f_ >> 6, bc_ = (f_ & 63) << 2;                            \
            cp_async16(&Bs[BUF][brow_][bc_],                                      \
                       conv_w + (size_t)((K0) + brow_) * 256 + bc_);              \
        }                                                                          \
        cp_commit();                                                               \
    } while (0)

    K1_ISSUE(0, 0);

#pragma unroll 1
    for (int kb = 0; kb < 16; kb++) {
        const int buf = kb & 1;
        if (kb < 15) { K1_ISSUE((kb + 1) * 16, buf ^ 1); cp_wait1(); }
        else         { cp_wait0(); }
        __syncthreads();

#pragma unroll
        for (int k = 0; k < 16; k++) {
            float4 a0 = *(const float4*)&As[buf][k][ty * 8];
            float4 a1 = *(const float4*)&As[buf][k][ty * 8 + 4];
            float4 b0 = *(const float4*)&Bs[buf][k][tx * 4];
            float4 b1 = *(const float4*)&Bs[buf][k][128 + tx * 4];
            float rm[8] = {a0.x, a0.y, a0.z, a0.w, a1.x, a1.y, a1.z, a1.w};
            float rn[8] = {b0.x, b0.y, b0.z, b0.w, b1.x, b1.y, b1.z, b1.w};
#pragma unroll
            for (int i = 0; i < 8; i++)
#pragma unroll
                for (int j = 0; j < 8; j++)
                    acc[i][j] = fmaf(rm[i], rn[j], acc[i][j]);
        }
        __syncthreads();
    }
#undef K1_ISSUE

    // ---- Epilogue: coords + bias + relu, store fused ----
    const int c0 = tx * 4;
    int cols[8];
#pragma unroll
    for (int j = 0; j < 8; j++) cols[j] = (j < 4) ? (c0 + j) : (128 + c0 + j - 4);

    const float* w256 = conv_w + 256 * 256;
    const float* w257 = conv_w + 257 * 256;
    float wx[8], wy[8], cb[8];
#pragma unroll
    for (int j = 0; j < 8; j++) {
        wx[j] = w256[cols[j]];
        wy[j] = w257[cols[j]];
        cb[j] = conv_b[cols[j]];
    }

    float* fbase = g_fused + ((size_t)b * HWL + hw0 + ty * 8) * 256;
#pragma unroll
    for (int i = 0; i < 8; i++) {
        const int hw = hw0 + ty * 8 + i;
        const int h  = hw / WW;
        const int w_ = hw - h * WW;
        const float xc = w_ * (1.0f / (WW - 1));
        const float yc = h  * (1.0f / (HH - 1));
#pragma unroll
        for (int j = 0; j < 8; j++) {
            float v = acc[i][j] + xc * wx[j] + yc * wy[j] + cb[j];
            acc[i][j] = fmaxf(v, 0.f);
        }
        float* fr = fbase + (size_t)i * 256;
        float4 s0 = make_float4(acc[i][0], acc[i][1], acc[i][2], acc[i][3]);
        float4 s1 = make_float4(acc[i][4], acc[i][5], acc[i][6], acc[i][7]);
        *(float4*)(fr + c0)       = s0;
        *(float4*)(fr + 128 + c0) = s1;
    }

    // ---- Scores from registers: warp-wide d-reduction ----
#pragma unroll 1
    for (int n = 0; n < NOBJ; n++) {
        const float* qn = query + n * 256;
        float qv[8];
#pragma unroll
        for (int j = 0; j < 8; j++) qv[j] = qn[cols[j]];
#pragma unroll
        for (int i = 0; i < 8; i++) {
            float p = 0.f;
#pragma unroll
            for (int j = 0; j < 8; j++) p = fmaf(qv[j], acc[i][j], p);
#pragma unroll
            for (int o = 16; o > 0; o >>= 1) p += __shfl_xor_sync(0xffffffffu, p, o);
            if (tx == 0)
                g_scores[((size_t)b * NOBJ + n) * HWL + hw0 + ty * 8 + i] = p;
        }
    }
}

// =====================================================================
// K2: one CTA per batch. softmax -> vals -> reps(+norm+mask) -> o1/o2 -> pair
// 256 threads; thread owns output channel c = tid.
// =====================================================================
__global__ __launch_bounds__(256)
void k2_rest(const float* __restrict__ feat_w, const float* __restrict__ feat_b,
             const float* __restrict__ o1w, const float* __restrict__ o1b,
             const float* __restrict__ o2w, const float* __restrict__ o2b,
             const int* __restrict__ olen_raw, float* __restrict__ out) {
    __shared__ float attn[NOBJ][HWL];
    __shared__ float vals_s[NOBJ][256];
    __shared__ float reps_s[NOBJ][256];
    __shared__ float red[NOBJ];

    const int b    = blockIdx.x;
    const int tid  = threadIdx.x;
    const int lane = tid & 31;
    const int wid  = tid >> 5;

    // ---- softmax over HW per (b,n): one warp per row ----
    for (int n = wid; n < NOBJ; n += 8) {
        const float* sc = g_scores + ((size_t)b * NOBJ + n) * HWL;
        float v[12];
        float mx = -1e30f;
#pragma unroll
        for (int r = 0; r < 12; r++) { v[r] = sc[lane + 32 * r]; mx = fmaxf(mx, v[r]); }
#pragma unroll
        for (int o = 16; o > 0; o >>= 1) mx = fmaxf(mx, __shfl_xor_sync(0xffffffffu, mx, o));
        float s = 0.f;
#pragma unroll
        for (int r = 0; r < 12; r++) { v[r] = __expf(v[r] - mx); s += v[r]; }
#pragma unroll
        for (int o = 16; o > 0; o >>= 1) s += __shfl_xor_sync(0xffffffffu, s, o);
        const float inv = 1.f / s;
#pragma unroll
        for (int r = 0; r < 12; r++) attn[n][lane + 32 * r] = v[r] * inv;
    }
    __syncthreads();

    // ---- vals[n][c] = sum_hw attn[n][hw]*fused[b][hw][c] ----
    float av[NOBJ];
#pragma unroll
    for (int n = 0; n < NOBJ; n++) av[n] = 0.f;
    const float* fb = g_fused + (size_t)b * (HWL * 256) + tid;
#pragma unroll 4
    for (int hw = 0; hw < HWL; hw++) {
        float f = fb[(size_t)hw * 256];
#pragma unroll
        for (int n = 0; n < NOBJ; n++) av[n] = fmaf(attn[n][hw], f, av[n]);
    }
#pragma unroll
    for (int n = 0; n < NOBJ; n++) vals_s[n][tid] = av[n];
    __syncthreads();

    // ---- reps = relu(vals @ feat_w + feat_b) ----
    float rp[NOBJ];
#pragma unroll
    for (int n = 0; n < NOBJ; n++) rp[n] = 0.f;
#pragma unroll 4
    for (int k = 0; k < 256; k++) {
        float w = feat_w[k * 256 + tid];
#pragma unroll
        for (int n = 0; n < NOBJ; n++) rp[n] = fmaf(vals_s[n][k], w, rp[n]);
    }
    const float fbv = feat_b[tid];
#pragma unroll
    for (int n = 0; n < NOBJ; n++) rp[n] = fmaxf(rp[n] + fbv, 0.f);

    // ---- L2 norm per n ----
    if (tid < NOBJ) red[tid] = 0.f;
    __syncthreads();
#pragma unroll
    for (int n = 0; n < NOBJ; n++) {
        float sq = rp[n] * rp[n];
#pragma unroll
        for (int o = 16; o > 0; o >>= 1) sq += __shfl_xor_sync(0xffffffffu, sq, o);
        if (lane == 0) atomicAdd(&red[n], sq);
    }
    __syncthreads();

    // ---- ragged length (robust to int32 vs int64 storage) ----
    // int64 little-endian with values 1..10 has zero high words; int32 values are all >=1.
    int L;
    {
        const int* pi = olen_raw;
        L = (pi[1] == 0 && pi[3] == 0) ? pi[2 * b] : pi[b];
    }

#pragma unroll
    for (int n = 0; n < NOBJ; n++) {
        float inv = 1.f / fmaxf(sqrtf(red[n]), 1e-12f);
        float r = (n < L) ? rp[n] * inv : 0.f;
        reps_s[n][tid] = r;
        out[((size_t)b * NOBJ + n) * 256 + tid] = r;
    }
    __syncthreads();

    // ---- o1/o2 GEMMs ----
    float a1[NOBJ], a2[NOBJ];
#pragma unroll
    for (int n = 0; n < NOBJ; n++) { a1[n] = 0.f; a2[n] = 0.f; }
#pragma unroll 4
    for (int k = 0; k < 256; k++) {
        float w1 = o1w[k * 256 + tid];
        float w2 = o2w[k * 256 + tid];
#pragma unroll
        for (int n = 0; n < NOBJ; n++) {
            float r = reps_s[n][k];
            a1[n] = fmaf(r, w1, a1[n]);
            a2[n] = fmaf(r, w2, a2[n]);
        }
    }
    const float bb1 = o1b[tid], bb2 = o2b[tid];
#pragma unroll
    for (int n = 0; n < NOBJ; n++) { a1[n] += bb1; a2[n] += bb2; }

    // ---- pair[b][i][j][c] = (o1[i][c]+o2[j][c]) * mask_i * mask_j ----
    float* pout = out + (size_t)BB * NOBJ * 256 + (size_t)b * (NOBJ * NOBJ * 256) + tid;
#pragma unroll
    for (int i = 0; i < NOBJ; i++) {
        const bool mi = (i < L);
#pragma unroll
        for (int j = 0; j < NOBJ; j++) {
            float v = (mi && (j < L)) ? (a1[i] + a2[j]) : 0.f;
            pout[(size_t)(i * NOBJ + j) * 256] = v;
        }
    }
}

// =====================================================================
// Launch
// =====================================================================
extern "C" void kernel_launch(void* const* d_in, const int* in_sizes, int n_in,
                              void* d_out, int out_size) {
    const float* input  = (const float*)d_in[0];
    // d_in[1] = objects (unused by the reference)
    const int*   olen   = (const int*)d_in[2];   // int32 or int64; probed in-kernel
    const float* query  = (const float*)d_in[3];
    const float* conv_w = (const float*)d_in[4];
    const float* conv_b = (const float*)d_in[5];
    const float* feat_w = (const float*)d_in[6];
    const float* feat_b = (const float*)d_in[7];
    const float* o1w    = (const float*)d_in[8];
    const float* o1b    = (const float*)d_in[9];
    const float* o2w    = (const float*)d_in[10];
    const float* o2b    = (const float*)d_in[11];
    float* out = (float*)d_out;

    dim3 g1(HWL / 64, BB);
    k1_conv_scores<<<g1, 256>>>(input, conv_w, conv_b, query);
    k2_rest<<<BB, 256>>>(feat_w, feat_b, o1w, o1b, o2w, o2b, olen, out);
}

// round 3
// speedup vs baseline: 1.3379x; 1.3379x over previous
#include <cuda_runtime.h>
#include <cuda_bf16.h>
#include <cstdint>

#define BB   1024
#define CC   256
#define HH   16
#define WW   24
#define HWL  384
#define NOBJ 10
#define DD   256

// Scratch (device globals)
__device__ float g_fused[(size_t)BB * HWL * CC];             // [B][HW][C]
__device__ float g_scores[(size_t)BB * NOBJ * HWL];          // [B][N][HW]
__device__ __nv_bfloat16 g_whi[256 * 256];                   // weights hi [d][c]
__device__ __nv_bfloat16 g_wlo[256 * 256];                   // weights lo [d][c]

// ---------------- helpers ----------------
__device__ __forceinline__ void cp_async16(void* smem, const void* g) {
    unsigned s = (unsigned)__cvta_generic_to_shared(smem);
    asm volatile("cp.async.cg.shared.global [%0], [%1], 16;\n" :: "r"(s), "l"(g));
}
__device__ __forceinline__ void cp_commit() { asm volatile("cp.async.commit_group;\n" ::: "memory"); }
__device__ __forceinline__ void cp_wait0()  { asm volatile("cp.async.wait_group 0;\n" ::: "memory"); }

__device__ __forceinline__ void ldsm_x4(uint32_t* r, uint32_t addr) {
    asm volatile("ldmatrix.sync.aligned.m8n8.x4.shared.b16 {%0,%1,%2,%3}, [%4];"
                 : "=r"(r[0]), "=r"(r[1]), "=r"(r[2]), "=r"(r[3]) : "r"(addr));
}
__device__ __forceinline__ void ldsm_x4_t(uint32_t* r, uint32_t addr) {
    asm volatile("ldmatrix.sync.aligned.m8n8.x4.trans.shared.b16 {%0,%1,%2,%3}, [%4];"
                 : "=r"(r[0]), "=r"(r[1]), "=r"(r[2]), "=r"(r[3]) : "r"(addr));
}
__device__ __forceinline__ void mma_bf16(float* c, const uint32_t* a, uint32_t b0, uint32_t b1) {
    asm volatile("mma.sync.aligned.m16n8k16.row.col.f32.bf16.bf16.f32 "
                 "{%0,%1,%2,%3}, {%4,%5,%6,%7}, {%8,%9}, {%0,%1,%2,%3};"
                 : "+f"(c[0]), "+f"(c[1]), "+f"(c[2]), "+f"(c[3])
                 : "r"(a[0]), "r"(a[1]), "r"(a[2]), "r"(a[3]), "r"(b0), "r"(b1));
}
__device__ __forceinline__ unsigned pack2(__nv_bfloat16 a, __nv_bfloat16 b) {
    __nv_bfloat162 t(a, b);
    return *reinterpret_cast<unsigned*>(&t);
}

// ---------------- smem layout (bytes) ----------------
// GEMM phase:  A hi [256 rows x 80B] @0, A lo @20480, B hi [32 x 144B] @40960, B lo @45568
// Epi phase :  fused_s [64 hw][260 f32] @0 (66560B), score partials @66560 (10240B)
// Persistent:  qt @76800 (12288B), cw @89088 (3072B)
#define OFF_AHI  0u
#define OFF_ALO  20480u
#define OFF_BHI  40960u
#define OFF_BLO  45568u
#define OFF_FS   0u
#define OFF_SC   66560u
#define OFF_QT   76800u
#define OFF_CW   89088u
#define SMEM_K1  92160u
#define FS_STRIDE 260

// =====================================================================
// k0: split conv_w[0:256] into bf16 hi/lo, transposed to [d][c]
// =====================================================================
__global__ void k0_wprep(const float* __restrict__ conv_w) {
    int idx = blockIdx.x * 256 + threadIdx.x;   // 65536
    int d = idx >> 8, c = idx & 255;
    float x = conv_w[(size_t)c * 256 + d];
    __nv_bfloat16 h = __float2bfloat16(x);
    __nv_bfloat16 l = __float2bfloat16(x - __bfloat162float(h));
    g_whi[idx] = h;
    g_wlo[idx] = l;
}

// =====================================================================
// K1: split-bf16 mma.sync GEMM D[d=256][hw=64] = W[d][c] * input[c][hw]
// + coords/bias/ReLU epilogue + scores.
// 256 threads = 8 warps in 4(m) x 2(n) grid; warp tile m64 x n32.
// =====================================================================
__global__ __launch_bounds__(256, 2)
void k1_conv_scores(const float* __restrict__ input,
                    const float* __restrict__ conv_w,
                    const float* __restrict__ conv_b,
                    const float* __restrict__ query) {
    extern __shared__ __align__(16) char sm[];
    const int tid  = threadIdx.x;
    const int lane = tid & 31;
    const int wid  = tid >> 5;
    const int wm   = wid >> 1;           // 0..3  -> d rows wm*64
    const int wn   = wid & 1;            // 0..1  -> hw cols wn*32
    const int b    = blockIdx.y;
    const int hw0  = blockIdx.x * 64;
    const uint32_t smb = (uint32_t)__cvta_generic_to_shared(sm);

    // persistent: query transposed (padded 12) + coord weights
    float* qt = (float*)(sm + OFF_QT);
    float* cw = (float*)(sm + OFF_CW);
    {
        int d = tid;
#pragma unroll
        for (int n = 0; n < NOBJ; n++) qt[d * 12 + n] = query[n * 256 + d];
        qt[d * 12 + 10] = 0.f; qt[d * 12 + 11] = 0.f;
        cw[d]       = conv_w[256 * 256 + d];
        cw[256 + d] = conv_w[257 * 256 + d];
        cw[512 + d] = conv_b[d];
    }

    float acc[16][4];
#pragma unroll
    for (int i = 0; i < 16; i++)
#pragma unroll
        for (int j = 0; j < 4; j++) acc[i][j] = 0.f;

    const int bc = tid >> 3;            // 0..31 (c row of B tile)
    const int bh = (tid & 7) * 8;       // hw chunk
    const float* Bg = input + (size_t)b * (CC * HWL) + hw0 + bh;

#pragma unroll 1
    for (int ks = 0; ks < 8; ks++) {
        const int kbase = ks * 32;
        __syncthreads();
        // ---- A tiles: cp.async bf16 hi/lo, row tid (64B -> padded 80B row) ----
        {
            const char* gh = (const char*)g_whi + (size_t)tid * 512 + kbase * 2;
            const char* gl = (const char*)g_wlo + (size_t)tid * 512 + kbase * 2;
#pragma unroll
            for (int j = 0; j < 4; j++) {
                cp_async16(sm + OFF_AHI + tid * 80 + j * 16, gh + j * 16);
                cp_async16(sm + OFF_ALO + tid * 80 + j * 16, gl + j * 16);
            }
            cp_commit();
        }
        // ---- B tile: load fp32 [c][hw], split to bf16 hi/lo in smem ----
        {
            const float* bp = Bg + (size_t)(kbase + bc) * HWL;
            float4 x0 = *(const float4*)bp;
            float4 x1 = *(const float4*)(bp + 4);
            float xs[8] = {x0.x, x0.y, x0.z, x0.w, x1.x, x1.y, x1.z, x1.w};
            unsigned hi[4], lo[4];
#pragma unroll
            for (int p = 0; p < 4; p++) {
                __nv_bfloat16 h0 = __float2bfloat16(xs[2 * p]);
                __nv_bfloat16 h1 = __float2bfloat16(xs[2 * p + 1]);
                __nv_bfloat16 l0 = __float2bfloat16(xs[2 * p]     - __bfloat162float(h0));
                __nv_bfloat16 l1 = __float2bfloat16(xs[2 * p + 1] - __bfloat162float(h1));
                hi[p] = pack2(h0, h1); lo[p] = pack2(l0, l1);
            }
            *(uint4*)(sm + OFF_BHI + bc * 144 + bh * 2) = make_uint4(hi[0], hi[1], hi[2], hi[3]);
            *(uint4*)(sm + OFF_BLO + bc * 144 + bh * 2) = make_uint4(lo[0], lo[1], lo[2], lo[3]);
        }
        cp_wait0();
        __syncthreads();

        // ---- MMA: two k16 sub-steps ----
#pragma unroll
        for (int s = 0; s < 2; s++) {
            const uint32_t arow = (uint32_t)(wm * 64 + (lane & 15)) * 80 + s * 32 + (lane >> 4) * 16;
            const uint32_t brow = (uint32_t)(s * 16 + (lane & 15)) * 144 + (wn * 32 + (lane >> 4) * 8) * 2;

            uint32_t ah[4][4], bhf[2][4];
#pragma unroll
            for (int mi = 0; mi < 4; mi++) ldsm_x4(ah[mi], smb + OFF_AHI + arow + mi * 16 * 80);
#pragma unroll
            for (int h = 0; h < 2; h++) ldsm_x4_t(bhf[h], smb + OFF_BHI + brow + h * 32);
#pragma unroll
            for (int mi = 0; mi < 4; mi++)
#pragma unroll
                for (int ni = 0; ni < 4; ni++)
                    mma_bf16(acc[mi * 4 + ni], ah[mi], bhf[ni >> 1][(ni & 1) * 2], bhf[ni >> 1][(ni & 1) * 2 + 1]);

            uint32_t blf[2][4];
#pragma unroll
            for (int h = 0; h < 2; h++) ldsm_x4_t(blf[h], smb + OFF_BLO + brow + h * 32);
#pragma unroll
            for (int mi = 0; mi < 4; mi++)
#pragma unroll
                for (int ni = 0; ni < 4; ni++)
                    mma_bf16(acc[mi * 4 + ni], ah[mi], blf[ni >> 1][(ni & 1) * 2], blf[ni >> 1][(ni & 1) * 2 + 1]);

            uint32_t al[4][4];
#pragma unroll
            for (int mi = 0; mi < 4; mi++) ldsm_x4(al[mi], smb + OFF_ALO + arow + mi * 16 * 80);
#pragma unroll
            for (int mi = 0; mi < 4; mi++)
#pragma unroll
                for (int ni = 0; ni < 4; ni++)
                    mma_bf16(acc[mi * 4 + ni], al[mi], bhf[ni >> 1][(ni & 1) * 2], bhf[ni >> 1][(ni & 1) * 2 + 1]);
        }
    }

    // ---- Epilogue: frags -> smem [hw][d] (stride 260) ----
    __syncthreads();
    float* fs = (float*)(sm + OFF_FS);
#pragma unroll
    for (int mi = 0; mi < 4; mi++)
#pragma unroll
        for (int ni = 0; ni < 4; ni++) {
            const float* a = acc[mi * 4 + ni];
            int d0  = wm * 64 + mi * 16 + (lane >> 2);
            int hwv = wn * 32 + ni * 8 + (lane & 3) * 2;
            fs[hwv * FS_STRIDE + d0]           = a[0];
            fs[(hwv + 1) * FS_STRIDE + d0]     = a[1];
            fs[hwv * FS_STRIDE + d0 + 8]       = a[2];
            fs[(hwv + 1) * FS_STRIDE + d0 + 8] = a[3];
        }
    __syncthreads();

    // ---- coords + bias + relu + scores (thread: hw = tid&63, d-quarter = tid>>6) ----
    {
        const int hwl = tid & 63;
        const int q   = tid >> 6;
        const int hw  = hw0 + hwl;
        const float xc = (float)(hw % WW) * (1.0f / (WW - 1));
        const float yc = (float)(hw / WW) * (1.0f / (HH - 1));
        float s[NOBJ];
#pragma unroll
        for (int n = 0; n < NOBJ; n++) s[n] = 0.f;

        float* row = fs + hwl * FS_STRIDE + q * 64;
#pragma unroll
        for (int j4 = 0; j4 < 16; j4++) {
            float4 v = *(float4*)(row + j4 * 4);
            float vv[4] = {v.x, v.y, v.z, v.w};
#pragma unroll
            for (int e = 0; e < 4; e++) {
                int d = q * 64 + j4 * 4 + e;
                float f = vv[e] + xc * cw[d] + yc * cw[256 + d] + cw[512 + d];
                f = fmaxf(f, 0.f);
                vv[e] = f;
                float4 q0 = *(const float4*)(qt + d * 12);
                float4 q1 = *(const float4*)(qt + d * 12 + 4);
                float4 q2 = *(const float4*)(qt + d * 12 + 8);
                s[0] = fmaf(q0.x, f, s[0]); s[1] = fmaf(q0.y, f, s[1]);
                s[2] = fmaf(q0.z, f, s[2]); s[3] = fmaf(q0.w, f, s[3]);
                s[4] = fmaf(q1.x, f, s[4]); s[5] = fmaf(q1.y, f, s[5]);
                s[6] = fmaf(q1.z, f, s[6]); s[7] = fmaf(q1.w, f, s[7]);
                s[8] = fmaf(q2.x, f, s[8]); s[9] = fmaf(q2.y, f, s[9]);
            }
            *(float4*)(row + j4 * 4) = make_float4(vv[0], vv[1], vv[2], vv[3]);
        }
        float* scp = (float*)(sm + OFF_SC);
#pragma unroll
        for (int n = 0; n < NOBJ; n++) scp[q * 640 + hwl * 10 + n] = s[n];
    }
    __syncthreads();

    // scores final reduce + store
    if (tid < 64) {
        float* scp = (float*)(sm + OFF_SC);
#pragma unroll
        for (int n = 0; n < NOBJ; n++) {
            float v = scp[tid * 10 + n] + scp[640 + tid * 10 + n]
                    + scp[1280 + tid * 10 + n] + scp[1920 + tid * 10 + n];
            g_scores[((size_t)b * NOBJ + n) * HWL + hw0 + tid] = v;
        }
    }

    // fused global store: fully coalesced (warp = 512B contiguous)
    {
        const int dchunk = tid & 63;
        const int hwb    = tid >> 6;
#pragma unroll
        for (int it = 0; it < 16; it++) {
            int hwr = hwb + it * 4;
            float4 v = *(float4*)(fs + hwr * FS_STRIDE + dchunk * 4);
            *(float4*)(g_fused + ((size_t)b * HWL + hw0 + hwr) * 256 + dchunk * 4) = v;
        }
    }
}

// =====================================================================
// K2: one CTA per batch. softmax -> vals -> reps(+norm+mask) -> o1/o2 -> pair
// =====================================================================
__global__ __launch_bounds__(256)
void k2_rest(const float* __restrict__ feat_w, const float* __restrict__ feat_b,
             const float* __restrict__ o1w, const float* __restrict__ o1b,
             const float* __restrict__ o2w, const float* __restrict__ o2b,
             const int* __restrict__ olen_raw, float* __restrict__ out) {
    __shared__ __align__(16) float attn_t[HWL][12];
    __shared__ float vals_s[NOBJ][256];
    __shared__ float reps_s[NOBJ][256];
    __shared__ float red[NOBJ];

    const int b    = blockIdx.x;
    const int tid  = threadIdx.x;
    const int lane = tid & 31;
    const int wid  = tid >> 5;

    // softmax per (b,n): one warp per row; transposed attn
    for (int n = wid; n < NOBJ; n += 8) {
        const float* sc = g_scores + ((size_t)b * NOBJ + n) * HWL;
        float v[12];
        float mx = -1e30f;
#pragma unroll
        for (int r = 0; r < 12; r++) { v[r] = sc[lane + 32 * r]; mx = fmaxf(mx, v[r]); }
#pragma unroll
        for (int o = 16; o > 0; o >>= 1) mx = fmaxf(mx, __shfl_xor_sync(0xffffffffu, mx, o));
        float ssum = 0.f;
#pragma unroll
        for (int r = 0; r < 12; r++) { v[r] = __expf(v[r] - mx); ssum += v[r]; }
#pragma unroll
        for (int o = 16; o > 0; o >>= 1) ssum += __shfl_xor_sync(0xffffffffu, ssum, o);
        const float inv = 1.f / ssum;
#pragma unroll
        for (int r = 0; r < 12; r++) attn_t[lane + 32 * r][n] = v[r] * inv;
    }
    __syncthreads();

    // vals[n][c]: batched loads (MLP=8)
    float av[NOBJ];
#pragma unroll
    for (int n = 0; n < NOBJ; n++) av[n] = 0.f;
    const float* fb = g_fused + (size_t)b * (HWL * 256) + tid;
#pragma unroll 1
    for (int hw8 = 0; hw8 < HWL; hw8 += 8) {
        float f[8];
#pragma unroll
        for (int r = 0; r < 8; r++) f[r] = fb[(size_t)(hw8 + r) * 256];
#pragma unroll
        for (int r = 0; r < 8; r++) {
            int hw = hw8 + r;
            float4 a0 = *(const float4*)&attn_t[hw][0];
            float4 a1 = *(const float4*)&attn_t[hw][4];
            float4 a2 = *(const float4*)&attn_t[hw][8];
            av[0] = fmaf(a0.x, f[r], av[0]); av[1] = fmaf(a0.y, f[r], av[1]);
            av[2] = fmaf(a0.z, f[r], av[2]); av[3] = fmaf(a0.w, f[r], av[3]);
            av[4] = fmaf(a1.x, f[r], av[4]); av[5] = fmaf(a1.y, f[r], av[5]);
            av[6] = fmaf(a1.z, f[r], av[6]); av[7] = fmaf(a1.w, f[r], av[7]);
            av[8] = fmaf(a2.x, f[r], av[8]); av[9] = fmaf(a2.y, f[r], av[9]);
        }
    }
#pragma unroll
    for (int n = 0; n < NOBJ; n++) vals_s[n][tid] = av[n];
    __syncthreads();

    // reps = relu(vals @ feat_w + feat_b), batched k
    float rp[NOBJ];
#pragma unroll
    for (int n = 0; n < NOBJ; n++) rp[n] = 0.f;
#pragma unroll 1
    for (int k4 = 0; k4 < 256; k4 += 4) {
        float w[4];
#pragma unroll
        for (int r = 0; r < 4; r++) w[r] = feat_w[(k4 + r) * 256 + tid];
#pragma unroll
        for (int r = 0; r < 4; r++)
#pragma unroll
            for (int n = 0; n < NOBJ; n++) rp[n] = fmaf(vals_s[n][k4 + r], w[r], rp[n]);
    }
    const float fbv = feat_b[tid];
#pragma unroll
    for (int n = 0; n < NOBJ; n++) rp[n] = fmaxf(rp[n] + fbv, 0.f);

    // L2 norm
    if (tid < NOBJ) red[tid] = 0.f;
    __syncthreads();
#pragma unroll
    for (int n = 0; n < NOBJ; n++) {
        float sq = rp[n] * rp[n];
#pragma unroll
        for (int o = 16; o > 0; o >>= 1) sq += __shfl_xor_sync(0xffffffffu, sq, o);
        if (lane == 0) atomicAdd(&red[n], sq);
    }
    __syncthreads();

    // ragged length (int32 vs int64 robust)
    int L;
    {
        const int* pi = olen_raw;
        L = (pi[1] == 0 && pi[3] == 0) ? pi[2 * b] : pi[b];
    }

#pragma unroll
    for (int n = 0; n < NOBJ; n++) {
        float inv = 1.f / fmaxf(sqrtf(red[n]), 1e-12f);
        float r = (n < L) ? rp[n] * inv : 0.f;
        reps_s[n][tid] = r;
        out[((size_t)b * NOBJ + n) * 256 + tid] = r;
    }
    __syncthreads();

    // o1/o2 GEMMs, batched k
    float a1v[NOBJ], a2v[NOBJ];
#pragma unroll
    for (int n = 0; n < NOBJ; n++) { a1v[n] = 0.f; a2v[n] = 0.f; }
#pragma unroll 1
    for (int k2 = 0; k2 < 256; k2 += 2) {
        float w1a = o1w[k2 * 256 + tid], w1b = o1w[(k2 + 1) * 256 + tid];
        float w2a = o2w[k2 * 256 + tid], w2b = o2w[(k2 + 1) * 256 + tid];
#pragma unroll
        for (int n = 0; n < NOBJ; n++) {
            float ra = reps_s[n][k2], rb = reps_s[n][k2 + 1];
            a1v[n] = fmaf(ra, w1a, a1v[n]); a1v[n] = fmaf(rb, w1b, a1v[n]);
            a2v[n] = fmaf(ra, w2a, a2v[n]); a2v[n] = fmaf(rb, w2b, a2v[n]);
        }
    }
    const float bb1 = o1b[tid], bb2 = o2b[tid];
#pragma unroll
    for (int n = 0; n < NOBJ; n++) { a1v[n] += bb1; a2v[n] += bb2; }

    float* pout = out + (size_t)BB * NOBJ * 256 + (size_t)b * (NOBJ * NOBJ * 256) + tid;
#pragma unroll
    for (int i = 0; i < NOBJ; i++) {
        const bool mi = (i < L);
#pragma unroll
        for (int j = 0; j < NOBJ; j++) {
            float v = (mi && (j < L)) ? (a1v[i] + a2v[j]) : 0.f;
            pout[(size_t)(i * NOBJ + j) * 256] = v;
        }
    }
}

// =====================================================================
extern "C" void kernel_launch(void* const* d_in, const int* in_sizes, int n_in,
                              void* d_out, int out_size) {
    const float* input  = (const float*)d_in[0];
    const int*   olen   = (const int*)d_in[2];
    const float* query  = (const float*)d_in[3];
    const float* conv_w = (const float*)d_in[4];
    const float* conv_b = (const float*)d_in[5];
    const float* feat_w = (const float*)d_in[6];
    const float* feat_b = (const float*)d_in[7];
    const float* o1w    = (const float*)d_in[8];
    const float* o1b    = (const float*)d_in[9];
    const float* o2w    = (const float*)d_in[10];
    const float* o2b    = (const float*)d_in[11];
    float* out = (float*)d_out;

    cudaFuncSetAttribute(k1_conv_scores, cudaFuncAttributeMaxDynamicSharedMemorySize, SMEM_K1);

    k0_wprep<<<256, 256>>>(conv_w);
    dim3 g1(HWL / 64, BB);
    k1_conv_scores<<<g1, 256, SMEM_K1>>>(input, conv_w, conv_b, query);
    k2_rest<<<BB, 256>>>(feat_w, feat_b, o1w, o1b, o2w, o2b, olen, out);
}